// round 1
// baseline (speedup 1.0000x reference)
#include <cuda_runtime.h>
#include <math.h>

#define BATCH 8
#define CH    128
#define NPIX  4096   // 64*64
#define BR    64
#define BC    64

// Scratch for Q, K, V in [b][c][n] layout (16 MB each). Static __device__
// arrays are the sanctioned no-alloc scratch mechanism.
__device__ float g_Q[BATCH * CH * NPIX];
__device__ float g_K[BATCH * CH * NPIX];
__device__ float g_V[BATCH * CH * NPIX];

typedef unsigned long long u64;

// ---- packed f32x2 helpers (sm_100+ PTX) ----
__device__ __forceinline__ void fma2(u64& d, u64 a, u64 b) {
    asm("fma.rn.f32x2 %0, %1, %2, %0;" : "+l"(d) : "l"(a), "l"(b));
}
__device__ __forceinline__ u64 mul2(u64 a, u64 b) {
    u64 d; asm("mul.rn.f32x2 %0, %1, %2;" : "=l"(d) : "l"(a), "l"(b)); return d;
}
__device__ __forceinline__ u64 pack2(float lo, float hi) {
    u64 d; asm("mov.b64 %0, {%1, %2};" : "=l"(d) : "f"(lo), "f"(hi)); return d;
}
__device__ __forceinline__ float2 unpack2(u64 a) {
    float2 r; asm("mov.b64 {%0, %1}, %2;" : "=f"(r.x), "=f"(r.y) : "l"(a)); return r;
}

// ============================================================
// QKV projection: out[b][o][p] = sum_c W[o][c] * X[b][c][p] + bias[o]
// grid (NPIX/128, 3, BATCH), 256 threads, classic 128x128 SGEMM tile (K=128)
// ============================================================
#define PROJ_SMEM_FLOATS (CH * 132 + CH * 128)

__global__ void __launch_bounds__(256, 1) qkv_kernel(
    const float* __restrict__ x1, const float* __restrict__ x2,
    const float* __restrict__ Wq, const float* __restrict__ bq,
    const float* __restrict__ Wk, const float* __restrict__ bk,
    const float* __restrict__ Wv, const float* __restrict__ bv)
{
    extern __shared__ float sm[];
    float* Wt = sm;             // [128][132]  transposed weights: Wt[c][o]
    float* Xs = sm + CH * 132;  // [128][128]  Xs[c][p]

    const int t  = threadIdx.x;
    const int tx = t & 15;
    const int ty = t >> 4;
    const int which = blockIdx.y;
    const int b     = blockIdx.z;
    const int p0    = blockIdx.x * 128;

    const float* X    = (which == 0 ? x1 : x2) + (size_t)b * CH * NPIX;
    const float* W    = (which == 0 ? Wq : (which == 1 ? Wk : Wv));
    const float* bias = (which == 0 ? bq : (which == 1 ? bk : bv));
    float* dst = (which == 0 ? g_Q : (which == 1 ? g_K : g_V)) + (size_t)b * CH * NPIX;

    // stage W transposed + X tile
#pragma unroll
    for (int it = 0; it < 8; ++it) {
        int oo = ty + 16 * it;
#pragma unroll
        for (int half = 0; half < 2; ++half) {
            int cc = 64 * half + 4 * tx;
            float4 w4 = *(const float4*)&W[oo * CH + cc];
            Wt[(cc + 0) * 132 + oo] = w4.x;
            Wt[(cc + 1) * 132 + oo] = w4.y;
            Wt[(cc + 2) * 132 + oo] = w4.z;
            Wt[(cc + 3) * 132 + oo] = w4.w;
        }
    }
#pragma unroll
    for (int it = 0; it < 8; ++it) {
        int cc = ty + 16 * it;
#pragma unroll
        for (int half = 0; half < 2; ++half) {
            int pp = 64 * half + 4 * tx;
            *(float4*)&Xs[cc * 128 + pp] = *(const float4*)&X[(size_t)cc * NPIX + p0 + pp];
        }
    }
    __syncthreads();

    float acc[8][8];
#pragma unroll
    for (int i = 0; i < 8; ++i)
#pragma unroll
        for (int j = 0; j < 8; ++j) acc[i][j] = 0.f;

#pragma unroll 4
    for (int c = 0; c < CH; ++c) {
        float4 wa = *(const float4*)&Wt[c * 132 + 4 * ty];
        float4 wb = *(const float4*)&Wt[c * 132 + 64 + 4 * ty];
        float4 xa = *(const float4*)&Xs[c * 128 + 4 * tx];
        float4 xb = *(const float4*)&Xs[c * 128 + 64 + 4 * tx];
        float wv[8] = {wa.x, wa.y, wa.z, wa.w, wb.x, wb.y, wb.z, wb.w};
        float xv[8] = {xa.x, xa.y, xa.z, xa.w, xb.x, xb.y, xb.z, xb.w};
#pragma unroll
        for (int i = 0; i < 8; ++i)
#pragma unroll
            for (int j = 0; j < 8; ++j)
                acc[i][j] = fmaf(wv[i], xv[j], acc[i][j]);
    }

#pragma unroll
    for (int i = 0; i < 8; ++i) {
        int o = (i < 4) ? (4 * ty + i) : (64 + 4 * ty + (i - 4));
        float bo = bias[o];
        float* dr = dst + (size_t)o * NPIX + p0;
        float4 r0 = make_float4(acc[i][0] + bo, acc[i][1] + bo, acc[i][2] + bo, acc[i][3] + bo);
        float4 r1 = make_float4(acc[i][4] + bo, acc[i][5] + bo, acc[i][6] + bo, acc[i][7] + bo);
        *(float4*)&dr[4 * tx]      = r0;
        *(float4*)&dr[64 + 4 * tx] = r1;
    }
}

// ============================================================
// Fused flash attention, fp32, f32x2-packed inner loops.
// grid (NPIX/BR, BATCH), 256 threads (tx 0..15 -> j/c tiles, ty 0..15 -> i rows)
//
// smem:
//   Qs2 [128][128]  dup-pairs: Qs2[c][2i],Qs2[c][2i+1] = Q[c][i]   (64 KB)
//   Ks  [128][64]   Ks[c][j]                                       (32 KB)
//   Vs  [64][132]   Vs[j][c] (transposed)                          (33 KB)
//   Ps  [64][132]   dup-pairs: Ps[j][2i] = P[i][j]                 (33 KB)
//   Os reuses Vs region: [128][66]
// ============================================================
#define ATTN_SMEM_FLOATS (128 * 128 + 128 * 64 + 64 * 132 + 64 * 132)

__global__ void __launch_bounds__(256, 1) attn_kernel(float* __restrict__ out)
{
    extern __shared__ float sm[];
    float* Qs2 = sm;                        // 16384 floats
    float* Ks  = sm + 16384;                //  8192 floats
    float* Vs  = sm + 16384 + 8192;         //  8448 floats
    float* Ps  = sm + 16384 + 8192 + 8448;  //  8448 floats

    const int t  = threadIdx.x;
    const int tx = t & 15;
    const int ty = t >> 4;
    const int b  = blockIdx.y;
    const int i0 = blockIdx.x * BR;

    const float* Qg = g_Q + (size_t)b * CH * NPIX;
    const float* Kg = g_K + (size_t)b * CH * NPIX;
    const float* Vg = g_V + (size_t)b * CH * NPIX;

    // ---- load Q tile as duplicated pairs ----
#pragma unroll
    for (int it = 0; it < 8; ++it) {
        int c = (t >> 4) + 16 * it;
        float4 q4 = *(const float4*)&Qg[(size_t)c * NPIX + i0 + 4 * (t & 15)];
        float* qb = &Qs2[c * 128 + 8 * (t & 15)];
        *(float4*)qb       = make_float4(q4.x, q4.x, q4.y, q4.y);
        *(float4*)(qb + 4) = make_float4(q4.z, q4.z, q4.w, q4.w);
    }

    float m[4], l[4];
#pragma unroll
    for (int ir = 0; ir < 4; ++ir) { m[ir] = -INFINITY; l[ir] = 0.f; }

    u64 op[4][4];  // O accumulators: rows i=4ty+ir, c-pairs c=8tx+2cp
#pragma unroll
    for (int ir = 0; ir < 4; ++ir)
#pragma unroll
        for (int cp = 0; cp < 4; ++cp) op[ir][cp] = 0ull;

    const float* qsp = Qs2 + 8 * ty;
    const float* ksp = Ks + 4 * tx;
    const float* psp = Ps + 8 * ty;
    const float* vsp = Vs + 8 * tx;

    for (int jt = 0; jt < NPIX / BC; ++jt) {
        const int j0 = jt * BC;
        __syncthreads();  // prior tile's readers done before overwrite

        // ---- stage K (straight) and V (transposed) tiles ----
#pragma unroll
        for (int it = 0; it < 8; ++it) {
            int c  = (t >> 4) + 16 * it;
            int jj = 4 * (t & 15);
            float4 k4 = *(const float4*)&Kg[(size_t)c * NPIX + j0 + jj];
            *(float4*)&Ks[c * 64 + jj] = k4;
            float4 v4 = *(const float4*)&Vg[(size_t)c * NPIX + j0 + jj];
            Vs[(jj + 0) * 132 + c] = v4.x;
            Vs[(jj + 1) * 132 + c] = v4.y;
            Vs[(jj + 2) * 132 + c] = v4.z;
            Vs[(jj + 3) * 132 + c] = v4.w;
        }
        __syncthreads();

        // ---- S = Q K^T  (pairs over j; q is dup-broadcast) ----
        u64 sp[4][2];
#pragma unroll
        for (int ir = 0; ir < 4; ++ir) { sp[ir][0] = 0ull; sp[ir][1] = 0ull; }

#pragma unroll 8
        for (int c = 0; c < CH; ++c) {
            ulonglong2 qa = *(const ulonglong2*)(qsp + c * 128);
            ulonglong2 qb = *(const ulonglong2*)(qsp + c * 128 + 4);
            ulonglong2 kp = *(const ulonglong2*)(ksp + c * 64);
            fma2(sp[0][0], qa.x, kp.x); fma2(sp[0][1], qa.x, kp.y);
            fma2(sp[1][0], qa.y, kp.x); fma2(sp[1][1], qa.y, kp.y);
            fma2(sp[2][0], qb.x, kp.x); fma2(sp[2][1], qb.x, kp.y);
            fma2(sp[3][0], qb.y, kp.x); fma2(sp[3][1], qb.y, kp.y);
        }

        // ---- online softmax (rows owned by ty; reduce across 16 tx lanes) ----
        float s[4][4];
#pragma unroll
        for (int ir = 0; ir < 4; ++ir) {
            float2 a  = unpack2(sp[ir][0]);
            float2 b2 = unpack2(sp[ir][1]);
            s[ir][0] = a.x; s[ir][1] = a.y; s[ir][2] = b2.x; s[ir][3] = b2.y;
        }
#pragma unroll
        for (int ir = 0; ir < 4; ++ir) {
            float mx = fmaxf(fmaxf(s[ir][0], s[ir][1]), fmaxf(s[ir][2], s[ir][3]));
#pragma unroll
            for (int o = 8; o >= 1; o >>= 1)
                mx = fmaxf(mx, __shfl_xor_sync(0xffffffffu, mx, o));
            float mn = fmaxf(m[ir], mx);
            float sc = __expf(m[ir] - mn);
            float rs = 0.f;
#pragma unroll
            for (int q = 0; q < 4; ++q) {
                s[ir][q] = __expf(s[ir][q] - mn);
                rs += s[ir][q];
            }
#pragma unroll
            for (int o = 8; o >= 1; o >>= 1)
                rs += __shfl_xor_sync(0xffffffffu, rs, o);
            l[ir] = l[ir] * sc + rs;
            m[ir] = mn;
            u64 scd = pack2(sc, sc);
#pragma unroll
            for (int cp = 0; cp < 4; ++cp) op[ir][cp] = mul2(op[ir][cp], scd);
        }

        // ---- write P duplicated: Ps[j][2i],Ps[j][2i+1] = P[i][j] ----
#pragma unroll
        for (int jq = 0; jq < 4; ++jq) {
            float* pr = Ps + (4 * tx + jq) * 132 + 8 * ty;
            *(float4*)pr       = make_float4(s[0][jq], s[0][jq], s[1][jq], s[1][jq]);
            *(float4*)(pr + 4) = make_float4(s[2][jq], s[2][jq], s[3][jq], s[3][jq]);
        }
        __syncthreads();

        // ---- O += P V  (pairs over c; p is dup-broadcast) ----
#pragma unroll 4
        for (int j = 0; j < BC; ++j) {
            ulonglong2 pd0 = *(const ulonglong2*)(psp + j * 132);
            ulonglong2 pd1 = *(const ulonglong2*)(psp + j * 132 + 4);
            ulonglong2 va  = *(const ulonglong2*)(vsp + j * 132);
            ulonglong2 vb  = *(const ulonglong2*)(vsp + j * 132 + 4);
            fma2(op[0][0], pd0.x, va.x); fma2(op[0][1], pd0.x, va.y);
            fma2(op[0][2], pd0.x, vb.x); fma2(op[0][3], pd0.x, vb.y);
            fma2(op[1][0], pd0.y, va.x); fma2(op[1][1], pd0.y, va.y);
            fma2(op[1][2], pd0.y, vb.x); fma2(op[1][3], pd0.y, vb.y);
            fma2(op[2][0], pd1.x, va.x); fma2(op[2][1], pd1.x, va.y);
            fma2(op[2][2], pd1.x, vb.x); fma2(op[2][3], pd1.x, vb.y);
            fma2(op[3][0], pd1.y, va.x); fma2(op[3][1], pd1.y, va.y);
            fma2(op[3][2], pd1.y, vb.x); fma2(op[3][3], pd1.y, vb.y);
        }
    }

    // ---- epilogue: normalize, transpose through smem, coalesced store ----
    __syncthreads();
    float* Os = Vs;  // reuse: [128][66]
#pragma unroll
    for (int ir = 0; ir < 4; ++ir) {
        float inv = 1.f / l[ir];
#pragma unroll
        for (int cp = 0; cp < 4; ++cp) {
            float2 v = unpack2(op[ir][cp]);
            int c = 8 * tx + 2 * cp;
            Os[(c    ) * 66 + 4 * ty + ir] = v.x * inv;
            Os[(c + 1) * 66 + 4 * ty + ir] = v.y * inv;
        }
    }
    __syncthreads();

    float* og = out + (size_t)b * CH * NPIX + i0;
#pragma unroll
    for (int it = 0; it < 8; ++it) {
        int c  = (t >> 4) + 16 * it;
        int ii = 4 * (t & 15);
        const float* osr = Os + c * 66 + ii;
        *(float4*)&og[(size_t)c * NPIX + ii] =
            make_float4(osr[0], osr[1], osr[2], osr[3]);
    }
}

// ============================================================
extern "C" void kernel_launch(void* const* d_in, const int* in_sizes, int n_in,
                              void* d_out, int out_size)
{
    const float* x1 = (const float*)d_in[0];
    const float* x2 = (const float*)d_in[1];
    const float* Wq = (const float*)d_in[2];
    const float* bq = (const float*)d_in[3];
    const float* Wk = (const float*)d_in[4];
    const float* bk = (const float*)d_in[5];
    const float* Wv = (const float*)d_in[6];
    const float* bv = (const float*)d_in[7];
    float* out = (float*)d_out;

    const int proj_smem = PROJ_SMEM_FLOATS * (int)sizeof(float);   // 133120 B
    const int attn_smem = ATTN_SMEM_FLOATS * (int)sizeof(float);   // 165888 B
    cudaFuncSetAttribute(qkv_kernel, cudaFuncAttributeMaxDynamicSharedMemorySize, proj_smem);
    cudaFuncSetAttribute(attn_kernel, cudaFuncAttributeMaxDynamicSharedMemorySize, attn_smem);

    qkv_kernel<<<dim3(NPIX / 128, 3, BATCH), 256, proj_smem>>>(x1, x2, Wq, bq, Wk, bk, Wv, bv);
    attn_kernel<<<dim3(NPIX / BR, BATCH), 256, attn_smem>>>(out);
}